// round 11
// baseline (speedup 1.0000x reference)
#include <cuda_runtime.h>
#include <cuda_bf16.h>
#include <cstdint>

// ---------------------------------------------------------------------------
// BarrierNet on GB300, round 11: persistent CTAs, all weights smem-resident.
//   grid = #SMs, 512 threads (16 warps), 223KB smem: 4 weight matrices (bf16,
//   converted in-kernel once) + ping-pong activation buffers. Each CTA loops
//   over ~tiles/SM 128-row tiles with zero weight staging and no in-place
//   gemm hazards. 4x4 warp tiling (32r x 32c), bf16 m16n8k16 mma.sync,
//   tanh.approx.f32 (proven numerics). x double-buffered via cp.async.
// ---------------------------------------------------------------------------

#define THREADS 512
#define TILE_ROWS 128
#define STRB 136            // bf16 elems per smem row -> bank permutation
#define ROWB (STRB * 2)     // 272 bytes per row
#define WB   34816          // one 128x272 weight matrix

// byte offsets into dynamic smem
#define OFF_W    0                      // 4 x WB = 139264
#define OFF_BUF0 139264
#define OFF_BUF1 174080
#define OFF_XS   208896                 // 2 x 3072 (x tile double buffer, f32)
#define OFF_B4   215040                 // 4 x 128 f32 biases
#define OFF_F1W  217088                 // 768 f32 fc1_w
#define OFF_F1B  220160                 // 128 f32 fc1_b
#define OFF_W31  220672                 // 384 f32
#define OFF_W32  222208                 // 256 f32
#define OFF_SML  223232                 // 17 f32: b31[0..2] b32[3..4] std[5..10] mean[11..16]
#define SMEM_BYTES 223360

__device__ __forceinline__ uint32_t smem_u32(const void* p) {
    uint32_t a;
    asm("{ .reg .u64 t; cvta.to.shared.u64 t, %1; cvt.u32.u64 %0, t; }"
        : "=r"(a) : "l"(p));
    return a;
}

__device__ __forceinline__ void ldsm4(uint32_t& r0, uint32_t& r1, uint32_t& r2, uint32_t& r3,
                                      uint32_t addr) {
    asm volatile("ldmatrix.sync.aligned.m8n8.x4.shared.b16 {%0,%1,%2,%3}, [%4];"
                 : "=r"(r0), "=r"(r1), "=r"(r2), "=r"(r3) : "r"(addr));
}

__device__ __forceinline__ void mma_bf16(float* c,
                                         uint32_t a0, uint32_t a1, uint32_t a2, uint32_t a3,
                                         uint32_t b0, uint32_t b1) {
    asm volatile(
        "mma.sync.aligned.m16n8k16.row.col.f32.bf16.bf16.f32 "
        "{%0,%1,%2,%3}, {%4,%5,%6,%7}, {%8,%9}, {%0,%1,%2,%3};\n"
        : "+f"(c[0]), "+f"(c[1]), "+f"(c[2]), "+f"(c[3])
        : "r"(a0), "r"(a1), "r"(a2), "r"(a3), "r"(b0), "r"(b1));
}

__device__ __forceinline__ uint32_t pack_bf2(float lo, float hi) {
    __nv_bfloat162 h = __floats2bfloat162_rn(lo, hi);
    return *reinterpret_cast<uint32_t*>(&h);
}
__device__ __forceinline__ float tanh_fast(float x) {
    asm("tanh.approx.f32 %0, %0;" : "+f"(x));
    return x;
}

// ---- one 128x128x128 layer: dst = tanh(src @ W^T + b), 4x4 warp tiling -----
// warp w: rows [32*(w&3), +32), cols [32*(w>>2), +32). src != dst, no internal
// barrier. Caller barriers before (src ready) and after (dst published).
__device__ __forceinline__ void gemm_tanh(char* sb, int src_off, int dst_off,
                                          uint32_t w_off, const float* __restrict__ bias,
                                          int warp, int lane) {
    const int rw = warp & 3, cw = warp >> 2;
    const int g = lane >> 2, tg = lane & 3;
    float acc[2][4][4];
    #pragma unroll
    for (int mt = 0; mt < 2; ++mt)
        #pragma unroll
        for (int t = 0; t < 4; ++t)
            acc[mt][t][0] = acc[mt][t][1] = acc[mt][t][2] = acc[mt][t][3] = 0.f;

    const uint32_t base = smem_u32(sb);
    const int l7 = lane & 7;
    const int rA = (((lane >> 3) & 1) << 3) + l7;
    const int kA = (lane >> 4) << 3;
    uint32_t aaddr0 = base + src_off + (rw * 32 + rA) * ROWB + kA * 2;
    uint32_t aaddr1 = aaddr0 + 16 * ROWB;
    const int rB = (((lane >> 4) & 1) << 3) + l7;
    const int kB = ((lane >> 3) & 1) << 3;
    uint32_t baddr = base + w_off + (cw * 32 + rB) * ROWB + kB * 2;

    #pragma unroll
    for (int kk = 0; kk < 8; ++kk) {
        uint32_t a0, a1, a2, a3, a4, a5, a6, a7;
        ldsm4(a0, a1, a2, a3, aaddr0 + kk * 32);
        ldsm4(a4, a5, a6, a7, aaddr1 + kk * 32);
        uint32_t b0, b1, b2, b3, b4, b5, b6, b7;
        ldsm4(b0, b1, b2, b3, baddr + kk * 32);
        ldsm4(b4, b5, b6, b7, baddr + 16 * ROWB + kk * 32);
        mma_bf16(acc[0][0], a0, a1, a2, a3, b0, b1);
        mma_bf16(acc[0][1], a0, a1, a2, a3, b2, b3);
        mma_bf16(acc[0][2], a0, a1, a2, a3, b4, b5);
        mma_bf16(acc[0][3], a0, a1, a2, a3, b6, b7);
        mma_bf16(acc[1][0], a4, a5, a6, a7, b0, b1);
        mma_bf16(acc[1][1], a4, a5, a6, a7, b2, b3);
        mma_bf16(acc[1][2], a4, a5, a6, a7, b4, b5);
        mma_bf16(acc[1][3], a4, a5, a6, a7, b6, b7);
    }

    #pragma unroll
    for (int mt = 0; mt < 2; ++mt) {
        char* o0 = sb + dst_off + (rw * 32 + mt * 16 + g) * ROWB + cw * 64;
        #pragma unroll
        for (int t = 0; t < 4; ++t) {
            int c = cw * 32 + t * 8 + tg * 2;
            float b0 = bias[c], b1 = bias[c + 1];
            uint32_t p0 = pack_bf2(tanh_fast(acc[mt][t][0] + b0), tanh_fast(acc[mt][t][1] + b1));
            uint32_t p1 = pack_bf2(tanh_fast(acc[mt][t][2] + b0), tanh_fast(acc[mt][t][3] + b1));
            *reinterpret_cast<uint32_t*>(o0 + (t * 8 + tg * 2) * 2) = p0;
            *reinterpret_cast<uint32_t*>(o0 + 8 * ROWB + (t * 8 + tg * 2) * 2) = p1;
        }
    }
}

// ---- fc1 (K=6) + tanh -> dst (bf16). 512 thr: col pair x 16 rows each ------
__device__ __forceinline__ void fc1_to(char* sb, int dst_off, const float* __restrict__ xs,
                                       int tid) {
    const float* w1s = reinterpret_cast<const float*>(sb + OFF_F1W);
    const float* b1s = reinterpret_cast<const float*>(sb + OFF_F1B);
    const int cp2  = tid & 63;         // column pair 0..63
    const int rblk = tid >> 6;         // row block 0..7 (16 rows each)
    const int c0 = 2 * cp2;
    const float* wA = &w1s[c0 * 6];
    const float* wB = wA + 6;
    float wa0 = wA[0], wa1 = wA[1], wa2 = wA[2], wa3 = wA[3], wa4 = wA[4], wa5 = wA[5];
    float wb0 = wB[0], wb1 = wB[1], wb2 = wB[2], wb3 = wB[3], wb4 = wB[4], wb5 = wB[5];
    float ba = b1s[c0], bb = b1s[c0 + 1];
    #pragma unroll
    for (int rr = 0; rr < 16; ++rr) {
        int row = rblk * 16 + rr;
        const float* xr = &xs[row * 6];
        float x0v = xr[0], x1v = xr[1], x2v = xr[2], x3v = xr[3], x4v = xr[4], x5v = xr[5];
        float sA = ba + x0v*wa0 + x1v*wa1 + x2v*wa2 + x3v*wa3 + x4v*wa4 + x5v*wa5;
        float sB = bb + x0v*wb0 + x1v*wb1 + x2v*wb2 + x3v*wb3 + x4v*wb4 + x5v*wb5;
        *reinterpret_cast<uint32_t*>(sb + dst_off + row * ROWB + cp2 * 4) =
            pack_bf2(tanh_fast(sA), tanh_fast(sB));
    }
}

__global__ void __launch_bounds__(THREADS, 1)
barriernet_kernel(const float* __restrict__ x,
                  const float* __restrict__ mean_, const float* __restrict__ std_,
                  const float* __restrict__ fc1_w, const float* __restrict__ fc1_b,
                  const float* __restrict__ fc21_w, const float* __restrict__ fc21_b,
                  const float* __restrict__ fc22_w, const float* __restrict__ fc22_b,
                  const float* __restrict__ fcm1_w, const float* __restrict__ fcm1_b,
                  const float* __restrict__ fcm2_w, const float* __restrict__ fcm2_b,
                  const float* __restrict__ fc31_w, const float* __restrict__ fc31_b,
                  const float* __restrict__ fc32_w, const float* __restrict__ fc32_b,
                  float* __restrict__ out, int ntiles)
{
    extern __shared__ char sb[];
    const int tid  = threadIdx.x;
    const int warp = tid >> 5;
    const int lane = tid & 31;
    const uint32_t base = smem_u32(sb);

    // ---- one-time staging: 4 weight matrices fp32 -> bf16 padded rows ------
    {
        const float* Wg[4] = {fc21_w, fcm1_w, fc22_w, fcm2_w};
        #pragma unroll
        for (int m = 0; m < 4; ++m) {
            const float4* W4 = reinterpret_cast<const float4*>(Wg[m]);
            #pragma unroll
            for (int i = tid; i < 4096; i += THREADS) {
                float4 v = W4[i];
                int row = i >> 5, c4 = i & 31;
                uint2 p = make_uint2(pack_bf2(v.x, v.y), pack_bf2(v.z, v.w));
                *reinterpret_cast<uint2*>(sb + OFF_W + m * WB + row * ROWB + c4 * 8) = p;
            }
        }
        float* b4 = reinterpret_cast<float*>(sb + OFF_B4);
        if (tid < 128) {
            b4[tid]       = fc21_b[tid];
            b4[128 + tid] = fcm1_b[tid];
            b4[256 + tid] = fc22_b[tid];
            b4[384 + tid] = fcm2_b[tid];
        }
        float* f1w = reinterpret_cast<float*>(sb + OFF_F1W);
        for (int i = tid; i < 768; i += THREADS) f1w[i] = fc1_w[i];
        float* f1b = reinterpret_cast<float*>(sb + OFF_F1B);
        if (tid >= 128 && tid < 256) f1b[tid - 128] = fc1_b[tid - 128];
        float* w31s = reinterpret_cast<float*>(sb + OFF_W31);
        if (tid >= 256 && tid < 256 + 384) w31s[tid - 256] = fc31_w[tid - 256];
        float* w32s = reinterpret_cast<float*>(sb + OFF_W32);
        if (tid >= 128 && tid < 384) w32s[tid - 128] = fc32_w[tid - 128];
        float* sml = reinterpret_cast<float*>(sb + OFF_SML);
        if (tid < 3)  sml[tid] = fc31_b[tid];
        if (tid >= 3 && tid < 5) sml[tid] = fc32_b[tid - 3];
        if (tid >= 5 && tid < 11) sml[tid] = std_[tid - 5];
        if (tid >= 11 && tid < 17) sml[tid] = mean_[tid - 11];
    }

    const float* b4   = reinterpret_cast<const float*>(sb + OFF_B4);
    const float* w31s = reinterpret_cast<const float*>(sb + OFF_W31);
    const float* w32s = reinterpret_cast<const float*>(sb + OFF_W32);
    const float* sml  = reinterpret_cast<const float*>(sb + OFF_SML);

    // prefetch first tile's x into xs buffer 0
    int t0 = blockIdx.x;
    if (t0 < ntiles && tid < 192) {
        asm volatile("cp.async.cg.shared.global [%0], [%1], 16;"
                     :: "r"(base + OFF_XS + tid * 16),
                        "l"(__cvta_generic_to_global(
                            reinterpret_cast<const char*>(x + (size_t)t0 * 768) + tid * 16)));
    }
    asm volatile("cp.async.commit_group;");

    int xb = 0;
    for (int t = t0; t < ntiles; t += gridDim.x) {
        asm volatile("cp.async.wait_group 0;");
        __syncthreads();                     // weights (first iter) + xs[xb] ready
        const float* xs = reinterpret_cast<const float*>(sb + OFF_XS + xb * 3072);

        // prefetch next tile's x into the other buffer
        int tn = t + gridDim.x;
        if (tn < ntiles && tid < 192) {
            asm volatile("cp.async.cg.shared.global [%0], [%1], 16;"
                         :: "r"(base + OFF_XS + (xb ^ 1) * 3072 + tid * 16),
                            "l"(__cvta_generic_to_global(
                                reinterpret_cast<const char*>(x + (size_t)tn * 768) + tid * 16)));
        }
        asm volatile("cp.async.commit_group;");

        // ---- path 1: fc1 -> fc21 -> fcm1 ----
        fc1_to(sb, OFF_BUF0, xs, tid);
        __syncthreads();
        gemm_tanh(sb, OFF_BUF0, OFF_BUF1, OFF_W + 0 * WB, b4 + 0,   warp, lane);
        __syncthreads();
        gemm_tanh(sb, OFF_BUF1, OFF_BUF0, OFF_W + 1 * WB, b4 + 128, warp, lane);
        __syncthreads();

        // ---- fc31 head (quad-split: row = tid>>2, k-quarter = tid&3) ----
        float d0, d1, d2;
        {
            const int row = tid >> 2, q = tid & 3;
            const uint32_t* a = reinterpret_cast<const uint32_t*>(sb + OFF_BUF0 + row * ROWB) + q * 16;
            float s0 = 0.f, s1 = 0.f, s2 = 0.f;
            #pragma unroll
            for (int i = 0; i < 16; ++i) {
                uint32_t u = a[i];
                float2 av = __bfloat1622float2(*reinterpret_cast<const __nv_bfloat162*>(&u));
                int k = q * 32 + 2 * i;
                s0 += av.x * w31s[k]       + av.y * w31s[k + 1];
                s1 += av.x * w31s[128 + k] + av.y * w31s[128 + k + 1];
                s2 += av.x * w31s[256 + k] + av.y * w31s[256 + k + 1];
            }
            s0 += __shfl_xor_sync(0xFFFFFFFF, s0, 1); s0 += __shfl_xor_sync(0xFFFFFFFF, s0, 2);
            s1 += __shfl_xor_sync(0xFFFFFFFF, s1, 1); s1 += __shfl_xor_sync(0xFFFFFFFF, s1, 2);
            s2 += __shfl_xor_sync(0xFFFFFFFF, s2, 1); s2 += __shfl_xor_sync(0xFFFFFFFF, s2, 2);
            d0 = s0 + sml[0]; d1 = s1 + sml[1]; d2 = s2 + sml[2];
        }
        // path 2 fc1 recompute into BUF1 (head reads BUF0 - disjoint)
        fc1_to(sb, OFF_BUF1, xs, tid);
        __syncthreads();

        // ---- path 2: fc22 -> fcm2 ----
        gemm_tanh(sb, OFF_BUF1, OFF_BUF0, OFF_W + 2 * WB, b4 + 256, warp, lane);
        __syncthreads();
        gemm_tanh(sb, OFF_BUF0, OFF_BUF1, OFF_W + 3 * WB, b4 + 384, warp, lane);
        __syncthreads();

        // ---- fc32 head + HOCBF/QP epilogue ----
        {
            const int row = tid >> 2, q = tid & 3;
            const uint32_t* a = reinterpret_cast<const uint32_t*>(sb + OFF_BUF1 + row * ROWB) + q * 16;
            float z0 = 0.f, z1 = 0.f;
            #pragma unroll
            for (int i = 0; i < 16; ++i) {
                uint32_t u = a[i];
                float2 av = __bfloat1622float2(*reinterpret_cast<const __nv_bfloat162*>(&u));
                int k = q * 32 + 2 * i;
                z0 += av.x * w32s[k]       + av.y * w32s[k + 1];
                z1 += av.x * w32s[128 + k] + av.y * w32s[128 + k + 1];
            }
            z0 += __shfl_xor_sync(0xFFFFFFFF, z0, 1); z0 += __shfl_xor_sync(0xFFFFFFFF, z0, 2);
            z1 += __shfl_xor_sync(0xFFFFFFFF, z1, 1); z1 += __shfl_xor_sync(0xFFFFFFFF, z1, 2);

            if (q == 0) {
                z0 += sml[3]; z1 += sml[4];
                float s0 = 4.f / (1.f + expf(-z0));
                float s1 = 4.f / (1.f + expf(-z1));

                const float* xr = &xs[row * 6];
                float px = xr[0] * sml[5]  + sml[11];
                float vx = xr[1] * sml[6]  + sml[12];
                float py = xr[2] * sml[7]  + sml[13];
                float vy = xr[3] * sml[8]  + sml[14];
                float pz = xr[4] * sml[9]  + sml[15];
                float vz = xr[5] * sml[10] + sml[16];

                float dx = px - 10.f, dy = py - 10.f, dz = pz - 9.f;
                float dx2 = dx*dx, dy2 = dy*dy, dz2 = dz*dz;
                float dx3 = dx2*dx, dy3 = dy2*dy, dz3 = dz2*dz;
                float barrier = dx2*dx2 + dy2*dy2 + dz2*dz2 - 2401.f;  // R^4 = 7^4
                float bdot = 4.f * (dx3*vx + dy3*vy + dz3*vz);
                float Lf2b = 12.f * (dx2*vx*vx + dy2*vy*vy + dz2*vz*vz);
                float Gx = -4.f*dx3, Gy = -4.f*dy3, Gz = -4.f*dz3;
                float hv = Lf2b + (s0 + s1) * bdot + s0 * s1 * barrier;

                float u0 = -d0, u1 = -d1, u2 = -d2;
                float Gu = Gx*u0 + Gy*u1 + Gz*u2;
                float GG = Gx*Gx + Gy*Gy + Gz*Gz;
                float lam = fmaxf(Gu - hv, 0.f) / GG;

                float* o = out + ((size_t)t * TILE_ROWS + row) * 3;
                o[0] = u0 - lam * Gx;
                o[1] = u1 - lam * Gy;
                o[2] = u2 - lam * Gz;
            }
        }
        __syncthreads();   // BUF1/xs reads done before next iteration overwrites
        xb ^= 1;
    }
}

extern "C" void kernel_launch(void* const* d_in, const int* in_sizes, int n_in,
                              void* d_out, int out_size) {
    const float* x      = (const float*)d_in[0];
    const float* mean_  = (const float*)d_in[1];
    const float* std_   = (const float*)d_in[2];
    const float* fc1_w  = (const float*)d_in[3];
    const float* fc1_b  = (const float*)d_in[4];
    const float* fc21_w = (const float*)d_in[5];
    const float* fc21_b = (const float*)d_in[6];
    const float* fc22_w = (const float*)d_in[7];
    const float* fc22_b = (const float*)d_in[8];
    const float* fcm1_w = (const float*)d_in[9];
    const float* fcm1_b = (const float*)d_in[10];
    const float* fcm2_w = (const float*)d_in[11];
    const float* fcm2_b = (const float*)d_in[12];
    const float* fc31_w = (const float*)d_in[13];
    const float* fc31_b = (const float*)d_in[14];
    const float* fc32_w = (const float*)d_in[15];
    const float* fc32_b = (const float*)d_in[16];
    float* out = (float*)d_out;

    int B = in_sizes[0] / 6;
    int ntiles = B / TILE_ROWS;

    int dev = 0, nsm = 148;
    cudaGetDevice(&dev);
    cudaDeviceGetAttribute(&nsm, cudaDevAttrMultiProcessorCount, dev);
    if (nsm > ntiles) nsm = ntiles;

    cudaFuncSetAttribute(barriernet_kernel,
                         cudaFuncAttributeMaxDynamicSharedMemorySize, SMEM_BYTES);
    barriernet_kernel<<<nsm, THREADS, SMEM_BYTES>>>(
        x, mean_, std_, fc1_w, fc1_b, fc21_w, fc21_b, fc22_w, fc22_b,
        fcm1_w, fcm1_b, fcm2_w, fcm2_b, fc31_w, fc31_b, fc32_w, fc32_b,
        out, ntiles);
}

// round 12
// speedup vs baseline: 1.1420x; 1.1420x over previous
#include <cuda_runtime.h>
#include <cuda_bf16.h>
#include <cstdint>

// ---------------------------------------------------------------------------
// BarrierNet on GB300, round 12: R3 (proven 84.5us) + two scoped deltas:
//   (1) load_w stages from pre-packed bf16 blobs (LDG.128 -> STS.128): half
//       the bytes, zero convert ops vs R3's fp32 LDG->convert->STS.
//   (2) tanh.approx.bf16x2 gemm epilogue (R4-validated numerics).
// Everything else is R3 verbatim: 256 thr, 2 CTA/SM, H+A buffers, 4x2 warp
// tiling, bf16 m16n8k16 mma.sync, per-layer synchronous staging.
// ---------------------------------------------------------------------------

#define THREADS 256
#define ROWS_PER_CTA 128
#define STRB 136            // bf16 elems per smem row (4g+tg bank permutation)
#define ROWB (STRB * 2)     // 272 bytes per row
#define WMAT_BYTES 34816    // 128*272
#define WMAT_CHUNKS (WMAT_BYTES / 16)   // 2176

// byte offsets into dynamic smem (R3 layout)
#define OFF_W    0                      // 128 x STRB bf16 = 34816 B
#define OFF_H    34816
#define OFF_A    69632
#define OFF_BIAS 104448                 // 128 f32
#define OFF_X    104960                 // 128*6 f32
#define OFF_W1   108032                 // 768 f32
#define OFF_B1   111104                 // 128 f32
#define OFF_W31  111616                 // 384 f32
#define OFF_W32  113152                 // 256 f32
#define OFF_SML  114176                 // 17 f32
#define SMEM_BYTES 114304

__device__ __align__(16) unsigned char g_wmat[4][WMAT_BYTES];
__device__ float g_wbias[4][128];

__device__ __forceinline__ uint32_t smem_u32(const void* p) {
    uint32_t a;
    asm("{ .reg .u64 t; cvta.to.shared.u64 t, %1; cvt.u32.u64 %0, t; }"
        : "=r"(a) : "l"(p));
    return a;
}

__device__ __forceinline__ void ldsm4(uint32_t& r0, uint32_t& r1, uint32_t& r2, uint32_t& r3,
                                      uint32_t addr) {
    asm volatile("ldmatrix.sync.aligned.m8n8.x4.shared.b16 {%0,%1,%2,%3}, [%4];"
                 : "=r"(r0), "=r"(r1), "=r"(r2), "=r"(r3) : "r"(addr));
}

__device__ __forceinline__ void mma_bf16(float& c0, float& c1, float& c2, float& c3,
                                         uint32_t a0, uint32_t a1, uint32_t a2, uint32_t a3,
                                         uint32_t b0, uint32_t b1) {
    asm volatile(
        "mma.sync.aligned.m16n8k16.row.col.f32.bf16.bf16.f32 "
        "{%0,%1,%2,%3}, {%4,%5,%6,%7}, {%8,%9}, {%0,%1,%2,%3};\n"
        : "+f"(c0), "+f"(c1), "+f"(c2), "+f"(c3)
        : "r"(a0), "r"(a1), "r"(a2), "r"(a3), "r"(b0), "r"(b1));
}

__device__ __forceinline__ float tanh_fast(float x) {
    asm("tanh.approx.f32 %0, %0;" : "+f"(x));
    return x;
}

__device__ __forceinline__ uint32_t pack_bf2(float lo, float hi) {
    __nv_bfloat162 h = __floats2bfloat162_rn(lo, hi);  // .x = lo (low 16 bits)
    return *reinterpret_cast<uint32_t*>(&h);
}

__device__ __forceinline__ uint32_t tanh2(uint32_t v) {
    asm("tanh.approx.bf16x2 %0, %0;" : "+r"(v));
    return v;
}

// ---------------- prep kernel: fp32 weights -> padded bf16 rows + biases ----
__global__ void prep_weights(const float* __restrict__ w21, const float* __restrict__ b21,
                             const float* __restrict__ wm1, const float* __restrict__ bm1,
                             const float* __restrict__ w22, const float* __restrict__ b22,
                             const float* __restrict__ wm2, const float* __restrict__ bm2) {
    const float* W[4]  = {w21, wm1, w22, wm2};
    const float* Bv[4] = {b21, bm1, b22, bm2};
    int m = blockIdx.x;
    unsigned char* dst = g_wmat[m];
    const float* src = W[m];
    // 128 rows x 68 u32 (64 data pairs + 4 pad pairs) -> same layout R3 built
    for (int i = threadIdx.x; i < 128 * 68; i += blockDim.x) {
        int r = i / 68, p = i % 68;
        uint32_t val = 0;
        if (p < 64) {
            float2 v = reinterpret_cast<const float2*>(src)[r * 64 + p];
            val = pack_bf2(v.x, v.y);
        }
        reinterpret_cast<uint32_t*>(dst + r * ROWB)[p] = val;
    }
    if (threadIdx.x < 128) g_wbias[m][threadIdx.x] = Bv[m][threadIdx.x];
}

// Stage one pre-packed bf16 weight matrix + fp32 bias into smem. Synchronous
// (R3 discipline); LDG.128 -> STS.128, half the bytes of R3's fp32 path.
__device__ __forceinline__ void load_w(char* sb, int midx, int tid) {
    __syncthreads();  // previous consumers of OFF_W done
    const uint4* g = reinterpret_cast<const uint4*>(g_wmat[midx]);
    uint4* w = reinterpret_cast<uint4*>(sb + OFF_W);
    #pragma unroll
    for (int it = 0; it < 9; ++it) {
        int i = tid + it * THREADS;
        if (i < WMAT_CHUNKS) w[i] = g[i];
    }
    if (tid < 128) reinterpret_cast<float*>(sb + OFF_BIAS)[tid] = g_wbias[midx][tid];
    __syncthreads();
}

// One 128x128x128 layer: out = tanh(in @ W^T + b), bf16 in/out, fp32 accum.
// R3's exact gemm; epilogue tanh via bf16x2. In-place safe (in_off == out_off).
__device__ __forceinline__ void gemm_tanh(char* sb, int in_off, int out_off,
                                          int warp, int lane) {
    const int rw = warp & 3, cw = warp >> 2;
    const int g = lane >> 2, tg = lane & 3;
    float acc[2][8][4];
    #pragma unroll
    for (int mt = 0; mt < 2; ++mt)
        #pragma unroll
        for (int t = 0; t < 8; ++t)
            acc[mt][t][0] = acc[mt][t][1] = acc[mt][t][2] = acc[mt][t][3] = 0.f;

    const uint32_t base = smem_u32(sb);
    const int l7 = lane & 7;
    const int rA = (((lane >> 3) & 1) << 3) + l7;
    const int kA = (lane >> 4) << 3;
    uint32_t aaddr0 = base + in_off + (rw * 32 + rA) * ROWB + kA * 2;
    uint32_t aaddr1 = aaddr0 + 16 * ROWB;
    const int rB = (((lane >> 4) & 1) << 3) + l7;
    const int kB = ((lane >> 3) & 1) << 3;
    uint32_t baddr = base + OFF_W + (cw * 64 + rB) * ROWB + kB * 2;

    #pragma unroll
    for (int kk = 0; kk < 8; ++kk) {
        uint32_t a0, a1, a2, a3, a4, a5, a6, a7;
        ldsm4(a0, a1, a2, a3, aaddr0 + kk * 32);
        ldsm4(a4, a5, a6, a7, aaddr1 + kk * 32);
        #pragma unroll
        for (int np = 0; np < 4; ++np) {
            uint32_t b0, b1, b2, b3;
            ldsm4(b0, b1, b2, b3, baddr + np * (16 * ROWB) + kk * 32);
            mma_bf16(acc[0][2*np][0],   acc[0][2*np][1],   acc[0][2*np][2],   acc[0][2*np][3],
                     a0, a1, a2, a3, b0, b1);
            mma_bf16(acc[0][2*np+1][0], acc[0][2*np+1][1], acc[0][2*np+1][2], acc[0][2*np+1][3],
                     a0, a1, a2, a3, b2, b3);
            mma_bf16(acc[1][2*np][0],   acc[1][2*np][1],   acc[1][2*np][2],   acc[1][2*np][3],
                     a4, a5, a6, a7, b0, b1);
            mma_bf16(acc[1][2*np+1][0], acc[1][2*np+1][1], acc[1][2*np+1][2], acc[1][2*np+1][3],
                     a4, a5, a6, a7, b2, b3);
        }
    }
    __syncwarp();  // all in-place reads complete before stores

    const float* bias = reinterpret_cast<const float*>(sb + OFF_BIAS);
    #pragma unroll
    for (int mt = 0; mt < 2; ++mt) {
        char* o0 = sb + out_off + (rw * 32 + mt * 16 + g) * ROWB + cw * 128;
        #pragma unroll
        for (int t = 0; t < 8; ++t) {
            int c = cw * 64 + t * 8 + tg * 2;
            float b0 = bias[c], b1 = bias[c + 1];
            uint32_t p0 = tanh2(pack_bf2(acc[mt][t][0] + b0, acc[mt][t][1] + b1));
            uint32_t p1 = tanh2(pack_bf2(acc[mt][t][2] + b0, acc[mt][t][3] + b1));
            *reinterpret_cast<uint32_t*>(o0 + (t * 8 + tg * 2) * 2) = p0;
            *reinterpret_cast<uint32_t*>(o0 + 8 * ROWB + (t * 8 + tg * 2) * 2) = p1;
        }
    }
    __syncwarp();
}

__global__ void __launch_bounds__(THREADS, 2)
barriernet_kernel(const float* __restrict__ x,
                  const float* __restrict__ mean_, const float* __restrict__ std_,
                  const float* __restrict__ fc1_w, const float* __restrict__ fc1_b,
                  const float* __restrict__ fc31_w, const float* __restrict__ fc31_b,
                  const float* __restrict__ fc32_w, const float* __restrict__ fc32_b,
                  float* __restrict__ out)
{
    extern __shared__ char sb[];
    const int tid  = threadIdx.x;
    const int warp = tid >> 5;
    const int lane = tid & 31;
    const int row0 = blockIdx.x * ROWS_PER_CTA;

    // ---- stage small constants + x tile (R3 verbatim) ----
    float* xs   = reinterpret_cast<float*>(sb + OFF_X);
    float* w1s  = reinterpret_cast<float*>(sb + OFF_W1);
    float* b1s  = reinterpret_cast<float*>(sb + OFF_B1);
    float* w31s = reinterpret_cast<float*>(sb + OFF_W31);
    float* w32s = reinterpret_cast<float*>(sb + OFF_W32);
    float* sml  = reinterpret_cast<float*>(sb + OFF_SML);
    for (int i = tid; i < 768; i += THREADS) { xs[i] = x[(size_t)row0 * 6 + i]; w1s[i] = fc1_w[i]; }
    for (int i = tid; i < 384; i += THREADS) w31s[i] = fc31_w[i];
    for (int i = tid; i < 256; i += THREADS) w32s[i] = fc32_w[i];
    if (tid < 128) b1s[tid] = fc1_b[tid];
    if (tid < 3)  sml[tid] = fc31_b[tid];
    if (tid >= 3 && tid < 5) sml[tid] = fc32_b[tid - 3];
    if (tid >= 5 && tid < 11) sml[tid] = std_[tid - 5];
    if (tid >= 11 && tid < 17) sml[tid] = mean_[tid - 11];
    __syncthreads();

    // ---- fc1 (K=6) + tanh -> H (bf16), R3 verbatim ----
    #pragma unroll
    for (int r = 0; r < 16; ++r) {
        int row = warp * 16 + r;
        const float* xr = &xs[row * 6];
        float x0v = xr[0], x1v = xr[1], x2v = xr[2], x3v = xr[3], x4v = xr[4], x5v = xr[5];
        #pragma unroll
        for (int c = lane; c < 128; c += 32) {
            const float* w = &w1s[c * 6];
            float s = b1s[c] + x0v*w[0] + x1v*w[1] + x2v*w[2] + x3v*w[3] + x4v*w[4] + x5v*w[5];
            *reinterpret_cast<__nv_bfloat16*>(sb + OFF_H + row * ROWB + c * 2) =
                __float2bfloat16_rn(tanh_fast(s));
        }
    }
    __syncwarp();

    // ---- path 1: fc21 -> fcm1 -> fc31 head (kept in registers) ----
    load_w(sb, 0, tid);
    gemm_tanh(sb, OFF_H, OFF_A, warp, lane);
    load_w(sb, 1, tid);
    gemm_tanh(sb, OFF_A, OFF_A, warp, lane);

    float d0 = 0.f, d1 = 0.f, d2 = 0.f;  // x31 for this lane's row (lanes 0..15)
    if (lane < 16) {
        int row = warp * 16 + lane;
        const uint32_t* a = reinterpret_cast<const uint32_t*>(sb + OFF_A + row * ROWB);
        d0 = sml[0]; d1 = sml[1]; d2 = sml[2];
        #pragma unroll 8
        for (int i = 0; i < 64; ++i) {
            uint32_t u = a[i];
            float2 av = __bfloat1622float2(*reinterpret_cast<const __nv_bfloat162*>(&u));
            int k = 2 * i;
            d0 += av.x * w31s[k]       + av.y * w31s[k + 1];
            d1 += av.x * w31s[128 + k] + av.y * w31s[128 + k + 1];
            d2 += av.x * w31s[256 + k] + av.y * w31s[256 + k + 1];
        }
    }
    __syncwarp();

    // ---- path 2: fc22 -> fcm2 -> fc32 head + HOCBF/QP epilogue ----
    load_w(sb, 2, tid);
    gemm_tanh(sb, OFF_H, OFF_A, warp, lane);
    load_w(sb, 3, tid);
    gemm_tanh(sb, OFF_A, OFF_A, warp, lane);

    if (lane < 16) {
        int row = warp * 16 + lane;
        const uint32_t* a = reinterpret_cast<const uint32_t*>(sb + OFF_A + row * ROWB);
        float z0 = sml[3], z1 = sml[4];
        #pragma unroll 8
        for (int i = 0; i < 64; ++i) {
            uint32_t u = a[i];
            float2 av = __bfloat1622float2(*reinterpret_cast<const __nv_bfloat162*>(&u));
            int k = 2 * i;
            z0 += av.x * w32s[k]       + av.y * w32s[k + 1];
            z1 += av.x * w32s[128 + k] + av.y * w32s[128 + k + 1];
        }
        float s0 = 4.f / (1.f + expf(-z0));
        float s1 = 4.f / (1.f + expf(-z1));

        const float* xr = &xs[row * 6];
        float px = xr[0] * sml[5] + sml[11];
        float vx = xr[1] * sml[6] + sml[12];
        float py = xr[2] * sml[7] + sml[13];
        float vy = xr[3] * sml[8] + sml[14];
        float pz = xr[4] * sml[9] + sml[15];
        float vz = xr[5] * sml[10] + sml[16];

        float dx = px - 10.f, dy = py - 10.f, dz = pz - 9.f;
        float dx2 = dx*dx, dy2 = dy*dy, dz2 = dz*dz;
        float dx3 = dx2*dx, dy3 = dy2*dy, dz3 = dz2*dz;
        float barrier = dx2*dx2 + dy2*dy2 + dz2*dz2 - 2401.f;  // R^4 = 7^4
        float bdot = 4.f * (dx3*vx + dy3*vy + dz3*vz);
        float Lf2b = 12.f * (dx2*vx*vx + dy2*vy*vy + dz2*vz*vz);
        float Gx = -4.f*dx3, Gy = -4.f*dy3, Gz = -4.f*dz3;
        float hv = Lf2b + (s0 + s1) * bdot + s0 * s1 * barrier;

        float u0 = -d0, u1 = -d1, u2 = -d2;
        float Gu = Gx*u0 + Gy*u1 + Gz*u2;
        float GG = Gx*Gx + Gy*Gy + Gz*Gz;
        float lam = fmaxf(Gu - hv, 0.f) / GG;

        float* o = out + (size_t)(row0 + row) * 3;
        o[0] = u0 - lam * Gx;
        o[1] = u1 - lam * Gy;
        o[2] = u2 - lam * Gz;
    }
}

extern "C" void kernel_launch(void* const* d_in, const int* in_sizes, int n_in,
                              void* d_out, int out_size) {
    const float* x      = (const float*)d_in[0];
    const float* mean_  = (const float*)d_in[1];
    const float* std_   = (const float*)d_in[2];
    const float* fc1_w  = (const float*)d_in[3];
    const float* fc1_b  = (const float*)d_in[4];
    const float* fc21_w = (const float*)d_in[5];
    const float* fc21_b = (const float*)d_in[6];
    const float* fc22_w = (const float*)d_in[7];
    const float* fc22_b = (const float*)d_in[8];
    const float* fcm1_w = (const float*)d_in[9];
    const float* fcm1_b = (const float*)d_in[10];
    const float* fcm2_w = (const float*)d_in[11];
    const float* fcm2_b = (const float*)d_in[12];
    const float* fc31_w = (const float*)d_in[13];
    const float* fc31_b = (const float*)d_in[14];
    const float* fc32_w = (const float*)d_in[15];
    const float* fc32_b = (const float*)d_in[16];
    float* out = (float*)d_out;

    int B = in_sizes[0] / 6;
    int grid = B / ROWS_PER_CTA;

    prep_weights<<<4, 256>>>(fc21_w, fc21_b, fcm1_w, fcm1_b,
                             fc22_w, fc22_b, fcm2_w, fcm2_b);

    cudaFuncSetAttribute(barriernet_kernel,
                         cudaFuncAttributeMaxDynamicSharedMemorySize, SMEM_BYTES);
    barriernet_kernel<<<grid, THREADS, SMEM_BYTES>>>(
        x, mean_, std_, fc1_w, fc1_b, fc31_w, fc31_b, fc32_w, fc32_b, out);
}